// round 13
// baseline (speedup 1.0000x reference)
#include <cuda_runtime.h>

// GroupWiseContrastiveLoss — factorized block means, 3-kernel pipeline.
//   S[i][j] = (sum clips_i) . (sum caps_j) / (nc[i]*na[j])
//   loss = sum_{i!=j} max(S[i][j]-diag[i],0) + max(S[i][j]-diag[j],0)
// Segment counts are always in [8, 24].

#define N_VID 256
#define DIM   1024
#define KQ    256   // DIM/4

// scratch (device globals — allocation is forbidden)
__device__ float  gA[N_VID * DIM];       // clip segment sums, row-major [i][k]
__device__ float4 gBT4[KQ * N_VID];      // cap segment sums, [k4][j] blocked-T
__device__ float  gS[N_VID * N_VID];     // divided block-mean matrix S
__device__ float  gPart[64];
__device__ unsigned gDone = 0;           // K3 last-block ticket (reset each run)

// ---- packed f32x2 helpers -------------------------------------------------
__device__ __forceinline__ void fma2(unsigned long long& acc,
                                     unsigned long long a,
                                     unsigned long long b) {
    asm("fma.rn.f32x2 %0, %1, %2, %0;" : "+l"(acc) : "l"(a), "l"(b));
}
__device__ __forceinline__ float hsum2(unsigned long long v) {
    float lo, hi;
    asm("mov.b64 {%0,%1}, %2;" : "=f"(lo), "=f"(hi) : "l"(v));
    return lo + hi;
}
__device__ __forceinline__ void acc4(float4& a, const float4& v) {
    a.x += v.x; a.y += v.y; a.z += v.z; a.w += v.w;
}

// ===== K1: segment sums =====================================================
// 512 blocks x 128 threads, 4 blocks/SM -> single wave on 148 SMs.
// Block b < 256: clip segment b -> gA. Block b >= 256: cap segment -> gBT4.
// Thread t owns column chunks t and t+128; 8-deep rolling prefetch on both
// -> 16 LDG.128 in flight per thread.
__global__ __launch_bounds__(128, 4) void k_segsum(
        const float* __restrict__ im, const float* __restrict__ s,
        const int* __restrict__ nclips, const int* __restrict__ ncaps) {
    __shared__ int sr[128];
    const int tid   = threadIdx.x;
    const int bid   = blockIdx.x;
    const bool isCap = (bid >= 256);
    const int seg   = bid & 255;
    const int* cnt  = isCap ? ncaps : nclips;

    // start offset = sum of cnt[t] for t < seg (reduction, not a scan)
    {
        int v = 0;
        if (tid < seg)        v  = cnt[tid];
        if (tid + 128 < seg)  v += cnt[tid + 128];
        sr[tid] = v;
        __syncthreads();
        #pragma unroll
        for (int o = 64; o > 0; o >>= 1) {
            if (tid < o) sr[tid] += sr[tid + o];
            __syncthreads();
        }
    }
    const int start = sr[0];
    const int c     = cnt[seg];   // in [8,24]

    const float4* base = reinterpret_cast<const float4*>(isCap ? s : im)
                         + (size_t)start * KQ;
    const float4* p0 = base + tid;
    const float4* p1 = base + tid + 128;

    // preload rows 0..7 on both chunks (c >= 8 always)
    float4 b0[8], b1[8];
    #pragma unroll
    for (int i = 0; i < 8; ++i) {
        b0[i] = p0[(size_t)i * KQ];
        b1[i] = p1[(size_t)i * KQ];
    }

    float4 a00 = make_float4(0.f,0.f,0.f,0.f), a01 = a00;
    float4 a10 = a00, a11 = a00;

    int r = 0;
    while (r + 16 <= c) {   // consume 8 buffered rows, prefetch next 8
        const float4* q0 = p0 + (size_t)(r + 8) * KQ;
        const float4* q1 = p1 + (size_t)(r + 8) * KQ;
        #pragma unroll
        for (int i = 0; i < 8; ++i) {
            float4 v0 = b0[i], v1 = b1[i];
            b0[i] = q0[(size_t)i * KQ];
            b1[i] = q1[(size_t)i * KQ];
            if (i & 1) { acc4(a01, v0); acc4(a11, v1); }
            else       { acc4(a00, v0); acc4(a10, v1); }
        }
        r += 8;
    }
    #pragma unroll
    for (int i = 0; i < 8; ++i) {   // drain buffered 8 rows
        if (i & 1) { acc4(a01, b0[i]); acc4(a11, b1[i]); }
        else       { acc4(a00, b0[i]); acc4(a10, b1[i]); }
    }
    r += 8;
    {   // tail: at most 7 rows, predicated batch of loads
        #pragma unroll
        for (int i = 0; i < 7; ++i) {
            if (r + i < c) {
                acc4(a00, p0[(size_t)(r + i) * KQ]);
                acc4(a10, p1[(size_t)(r + i) * KQ]);
            }
        }
    }

    const float4 A = make_float4(a00.x + a01.x, a00.y + a01.y,
                                 a00.z + a01.z, a00.w + a01.w);
    const float4 B = make_float4(a10.x + a11.x, a10.y + a11.y,
                                 a10.z + a11.z, a10.w + a11.w);
    if (isCap) {
        gBT4[tid * N_VID + seg]         = A;   // [k4][j]
        gBT4[(tid + 128) * N_VID + seg] = B;
    } else {
        float4* ga = reinterpret_cast<float4*>(gA) + (size_t)seg * KQ;
        ga[tid]       = A;
        ga[tid + 128] = B;
    }
}

// ===== K2: 256x256x1024 GEMM -> divided S matrix ============================
// 128 blocks own a 16i x 32j tile (halves L2 B-traffic vs 8i tiles).
// Warp w covers k4 in [32w, 32w+32). Each thread: one j, 16 i-accumulators.
__global__ __launch_bounds__(256, 1) void k_gemm(
        const int* __restrict__ nclips, const int* __restrict__ ncaps) {
    __shared__ float4 sA[16 * KQ];      // 64 KB A tile
    __shared__ float  sP[8 * 16 * 32];  // [warp][i][lane] partials, 16 KB

    const int tid  = threadIdx.x;
    const int bid  = blockIdx.x;
    const int i0   = (bid >> 3) * 16;   // 16 i-tiles
    const int j0   = (bid & 7) * 32;    // 8 j-slices
    const int warp = tid >> 5;
    const int lane = tid & 31;

    const float4* a4 = reinterpret_cast<const float4*>(gA) + (size_t)i0 * KQ;
    for (int t = tid; t < 16 * KQ; t += 256) sA[t] = a4[t];
    __syncthreads();

    const int jl = j0 + lane;
    const ulonglong2* bt = reinterpret_cast<const ulonglong2*>(gBT4);
    const ulonglong2* sa = reinterpret_cast<const ulonglong2*>(sA);

    unsigned long long accx[16], accy[16];
    #pragma unroll
    for (int i = 0; i < 16; ++i) { accx[i] = 0ull; accy[i] = 0ull; }

    const int k4b = warp * 32;
    ulonglong2 bbuf[2];
    bbuf[0] = bt[(k4b + 0) * N_VID + jl];
    bbuf[1] = bt[(k4b + 1) * N_VID + jl];
    #pragma unroll 4
    for (int kk = 0; kk < 32; ++kk) {
        const int k4 = k4b + kk;
        ulonglong2 bv = bbuf[kk & 1];
        if (kk + 2 < 32) bbuf[kk & 1] = bt[(k4 + 2) * N_VID + jl];
        #pragma unroll
        for (int i = 0; i < 16; ++i) {
            ulonglong2 av = sa[i * KQ + k4];   // broadcast LDS.128
            fma2(accx[i], av.x, bv.x);
            fma2(accy[i], av.y, bv.y);
        }
    }

    #pragma unroll
    for (int i = 0; i < 16; ++i)
        sP[warp * 512 + i * 32 + lane] = hsum2(accx[i]) + hsum2(accy[i]);
    __syncthreads();

    // 512 outputs, 256 threads -> each thread owns 2 (i,j) pairs.
    // thread t: (iA = t>>5, j) and (iB = iA + 8, j), fixed-order 8-warp sum.
    #pragma unroll
    for (int q = 0; q < 2; ++q) {
        const int il = (tid >> 5) + q * 8;
        float v = sP[il * 32 + lane];
        #pragma unroll
        for (int w = 1; w < 8; ++w) v += sP[w * 512 + il * 32 + lane];
        const int gi = i0 + il;
        const int j  = j0 + lane;
        gS[gi * N_VID + j] = v / ((float)nclips[gi] * (float)ncaps[j]);
    }
}

// ===== K3: hinge loss + deterministic reduce ================================
// 64 blocks x 256 threads; block handles 4 rows of S. Diagonal gathered to
// smem once per block. Last block out does the final 64-partial reduce.
__global__ __launch_bounds__(256) void k_loss(float* __restrict__ out) {
    __shared__ float sdiag[N_VID];
    __shared__ float sred[256];
    __shared__ unsigned sLast;

    const int tid = threadIdx.x;
    const int bid = blockIdx.x;

    sdiag[tid] = gS[tid * (N_VID + 1)];   // S[t][t]
    __syncthreads();

    const int i  = bid * 4 + (tid >> 6);
    const int j4 = (tid & 63) * 4;
    const float4 sv = reinterpret_cast<const float4*>(gS)[i * (N_VID / 4) + (tid & 63)];
    const float di = sdiag[i];

    float contrib = 0.f;
    {
        const float v[4] = {sv.x, sv.y, sv.z, sv.w};
        #pragma unroll
        for (int q = 0; q < 4; ++q) {
            const int j = j4 + q;
            if (j != i)
                contrib += fmaxf(v[q] - di, 0.f) + fmaxf(v[q] - sdiag[j], 0.f);
        }
    }

    sred[tid] = contrib;
    __syncthreads();
    for (int o = 128; o > 0; o >>= 1) {
        if (tid < o) sred[tid] += sred[tid + o];
        __syncthreads();
    }
    if (tid == 0) gPart[bid] = sred[0];

    // last-block-out final reduce
    if (tid == 0) {
        __threadfence();
        sLast = (atomicAdd(&gDone, 1u) == 63u) ? 1u : 0u;
    }
    __syncthreads();
    if (sLast) {
        if (tid == 0) __threadfence();
        __syncthreads();
        sred[tid] = (tid < 64) ? gPart[tid] : 0.f;
        __syncthreads();
        for (int o = 128; o > 0; o >>= 1) {
            if (tid < o) sred[tid] += sred[tid + o];
            __syncthreads();
        }
        if (tid == 0) {
            out[0] = sred[0];
            gDone  = 0;    // replay-safe reset
        }
    }
}

extern "C" void kernel_launch(void* const* d_in, const int* in_sizes, int n_in,
                              void* d_out, int out_size) {
    const float* im     = (const float*)d_in[0];
    const float* s      = (const float*)d_in[1];
    const int*   nclips = (const int*)d_in[2];
    const int*   ncaps  = (const int*)d_in[3];
    float*       out    = (float*)d_out;

    k_segsum<<<512, 128>>>(im, s, nclips, ncaps);
    k_gemm  <<<128, 256>>>(nclips, ncaps);
    k_loss  <<<64, 256>>>(out);
}